// round 13
// baseline (speedup 1.0000x reference)
#include <cuda_runtime.h>
#include <cuda_bf16.h>
#include <stdint.h>
#include <math.h>

#define TOK 8192
#define HID 1024
#define RNK 256
#define FFN 4096
#define NE  8
#define ERK (NE*RNK)  // 2048
#define NPAIR 28
#define MAXT1 136
#define MAXT2 92

#define NTHREADS 512
#define ROWB 80
#define A_T (128*ROWB)            // 10240
#define B_T (256*ROWB)            // 20480
#define STG (2*A_T + 2*B_T)       // 61440
#define SMEM_BYTES (3*STG)        // 184320 (3-stage pipeline)

// ---------------------------------------------------------------------------
// Scratch (device globals)
// ---------------------------------------------------------------------------
__device__ float g_mw[TOK * NE];
__device__ int g_e0t[TOK], g_e1t[TOK], g_pidt[TOK];
__device__ int g_pcnt[NPAIR], g_poff[NPAIR], g_pfill[NPAIR], g_ptok[TOK];
__device__ int g_ecnt[NE], g_eoff[NE], g_efill[NE], g_etok[2 * TOK];
__device__ int g_t1grp[MAXT1], g_t1row[MAXT1];
__device__ int g_t2grp[MAXT2], g_t2row[MAXT2];
__device__ int g_pe0[NPAIR], g_pe1[NPAIR];
__device__ int g_meta[2];

__device__ __nv_bfloat16 g_xh[(size_t)TOK * HID], g_xl[(size_t)TOK * HID];
__device__ __nv_bfloat16 g_th[(size_t)TOK * ERK], g_tl[(size_t)TOK * ERK];
__device__ __nv_bfloat16 g_hh[(size_t)TOK * FFN], g_hl[(size_t)TOK * FFN];
__device__ __nv_bfloat16 g_w1h[(size_t)ERK * HID], g_w1l[(size_t)ERK * HID];
__device__ __nv_bfloat16 g_w2h[(size_t)FFN * ERK], g_w2l[(size_t)FFN * ERK];
__device__ __nv_bfloat16 g_w3h[(size_t)HID * FFN], g_w3l[(size_t)HID * FFN];

// ---------------------------------------------------------------------------
// PTX helpers (base sm_103 target)
// ---------------------------------------------------------------------------
__device__ __forceinline__ uint32_t s2u(const void* p) {
    uint32_t a;
    asm("{ .reg .u64 t; cvta.to.shared.u64 t, %1; cvt.u32.u64 %0, t; }" : "=r"(a) : "l"(p));
    return a;
}
__device__ __forceinline__ void cp16(uint32_t dst, const void* src) {
    asm volatile("cp.async.cg.shared.global [%0], [%1], 16;" :: "r"(dst), "l"(src) : "memory");
}
__device__ __forceinline__ void cp_commit() {
    asm volatile("cp.async.commit_group;" ::: "memory");
}
template <int N>
__device__ __forceinline__ void cp_wait() {
    asm volatile("cp.async.wait_group %0;" :: "n"(N) : "memory");
}
__device__ __forceinline__ void ldsm4(uint32_t* r, uint32_t addr) {
    asm volatile("ldmatrix.sync.aligned.m8n8.x4.shared.b16 {%0,%1,%2,%3}, [%4];"
                 : "=r"(r[0]), "=r"(r[1]), "=r"(r[2]), "=r"(r[3]) : "r"(addr));
}
__device__ __forceinline__ void mma16816(float* c, const uint32_t* a, const uint32_t* b) {
    asm volatile(
        "mma.sync.aligned.m16n8k16.row.col.f32.bf16.bf16.f32 "
        "{%0,%1,%2,%3}, {%4,%5,%6,%7}, {%8,%9}, {%0,%1,%2,%3};"
        : "+f"(c[0]), "+f"(c[1]), "+f"(c[2]), "+f"(c[3])
        : "r"(a[0]), "r"(a[1]), "r"(a[2]), "r"(a[3]), "r"(b[0]), "r"(b[1]));
}
__device__ __forceinline__ void split_bf16(float v, __nv_bfloat16& hi, __nv_bfloat16& lo) {
    hi = __float2bfloat16(v);
    lo = __float2bfloat16(v - __bfloat162float(hi));
}

// ---------------------------------------------------------------------------
// Routing infrastructure
// ---------------------------------------------------------------------------
__global__ void zero_kernel() {
    int i = threadIdx.x;
    if (i < NPAIR) { g_pcnt[i] = 0; g_pfill[i] = 0; }
    if (i < NE)    { g_ecnt[i] = 0; g_efill[i] = 0; }
}

__global__ void router_kernel(const float* __restrict__ x,
                              const float* __restrict__ rw,
                              const float* __restrict__ rb) {
    int warp = (blockIdx.x * blockDim.x + threadIdx.x) >> 5;
    int lane = threadIdx.x & 31;
    if (warp >= TOK) return;

    const float4* xr = reinterpret_cast<const float4*>(x + (size_t)warp * HID);
    float acc[NE];
#pragma unroll
    for (int e = 0; e < NE; e++) acc[e] = 0.f;

    for (int i = lane; i < HID / 4; i += 32) {
        float4 xv = xr[i];
        int h = i * 4;
        const float4* w0 = reinterpret_cast<const float4*>(rw + (size_t)h * NE);
        float4 a0 = w0[0], a1 = w0[1];
        float4 b0 = w0[2], b1 = w0[3];
        float4 c0 = w0[4], c1 = w0[5];
        float4 d0 = w0[6], d1 = w0[7];
        acc[0] += xv.x*a0.x + xv.y*b0.x + xv.z*c0.x + xv.w*d0.x;
        acc[1] += xv.x*a0.y + xv.y*b0.y + xv.z*c0.y + xv.w*d0.y;
        acc[2] += xv.x*a0.z + xv.y*b0.z + xv.z*c0.z + xv.w*d0.z;
        acc[3] += xv.x*a0.w + xv.y*b0.w + xv.z*c0.w + xv.w*d0.w;
        acc[4] += xv.x*a1.x + xv.y*b1.x + xv.z*c1.x + xv.w*d1.x;
        acc[5] += xv.x*a1.y + xv.y*b1.y + xv.z*c1.y + xv.w*d1.y;
        acc[6] += xv.x*a1.z + xv.y*b1.z + xv.z*c1.z + xv.w*d1.z;
        acc[7] += xv.x*a1.w + xv.y*b1.w + xv.z*c1.w + xv.w*d1.w;
    }
#pragma unroll
    for (int e = 0; e < NE; e++) {
#pragma unroll
        for (int o = 16; o > 0; o >>= 1)
            acc[e] += __shfl_xor_sync(0xffffffffu, acc[e], o);
    }
    if (lane == 0) {
        float lg[NE], m = -1e30f;
#pragma unroll
        for (int e = 0; e < NE; e++) { lg[e] = acc[e] + rb[e]; m = fmaxf(m, lg[e]); }
        float p[NE], s = 0.f;
#pragma unroll
        for (int e = 0; e < NE; e++) { p[e] = expf(lg[e] - m); s += p[e]; }
        float inv = 1.f / s;
        int i0 = 0;
#pragma unroll
        for (int e = 1; e < NE; e++) if (p[e] > p[i0]) i0 = e;
        int i1 = (i0 == 0) ? 1 : 0;
#pragma unroll
        for (int e = 0; e < NE; e++) { if (e == i0) continue; if (p[e] > p[i1]) i1 = e; }
#pragma unroll
        for (int e = 0; e < NE; e++)
            g_mw[warp * NE + e] = (e == i0 || e == i1) ? p[e] * inv : 0.f;
        int e0 = min(i0, i1), e1 = max(i0, i1);
        int pid = e0 * (2 * NE - e0 - 1) / 2 + (e1 - e0 - 1);
        g_e0t[warp] = e0; g_e1t[warp] = e1; g_pidt[warp] = pid;
        atomicAdd(&g_pcnt[pid], 1);
        atomicAdd(&g_ecnt[e0], 1);
        atomicAdd(&g_ecnt[e1], 1);
    }
}

// scatter + integrated planning (plan_kernel eliminated)
__global__ void scatter_kernel() {
    __shared__ int s_eoff[NE], s_poff[NPAIR];
    if (threadIdx.x == 0) {
        int off = 0;
#pragma unroll
        for (int e2 = 0; e2 < NE; e2++) { s_eoff[e2] = off; off += g_ecnt[e2]; }
        off = 0;
#pragma unroll
        for (int p = 0; p < NPAIR; p++) { s_poff[p] = off; off += g_pcnt[p]; }
    }
    __syncthreads();

    // block 0 writes the global plan tables (gemm kernels read after this kernel)
    if (blockIdx.x == 0 && threadIdx.x == 0) {
        int nt = 0;
        for (int e2 = 0; e2 < NE; e2++) {
            g_eoff[e2] = s_eoff[e2];
            for (int r = 0; r < g_ecnt[e2]; r += 128) { g_t1grp[nt] = e2; g_t1row[nt] = r; nt++; }
        }
        g_meta[0] = nt;
        nt = 0;
        int p = 0;
        for (int a = 0; a < NE; a++)
            for (int b = a + 1; b < NE; b++) {
                g_pe0[p] = a; g_pe1[p] = b; g_poff[p] = s_poff[p];
                for (int r = 0; r < g_pcnt[p]; r += 128) { g_t2grp[nt] = p; g_t2row[nt] = r; nt++; }
                p++;
            }
        g_meta[1] = nt;
    }

    int t = blockIdx.x * blockDim.x + threadIdx.x;
    if (t >= TOK) return;
    int pid = g_pidt[t];
    int pos = atomicAdd(&g_pfill[pid], 1);
    g_ptok[s_poff[pid] + pos] = t;
    int e0 = g_e0t[t], e1 = g_e1t[t];
    pos = atomicAdd(&g_efill[e0], 1); g_etok[s_eoff[e0] + pos] = t;
    pos = atomicAdd(&g_efill[e1], 1); g_etok[s_eoff[e1] + pos] = t;
}

// ---------------------------------------------------------------------------
// Fused conversion kernel: x-split + 3 weight transposes in ONE launch
// ---------------------------------------------------------------------------
__device__ __forceinline__ void transpose_tile(const float* __restrict__ W,
                                               __nv_bfloat16* __restrict__ oh,
                                               __nv_bfloat16* __restrict__ ol,
                                               int K, int N, int k0, int n0,
                                               float (*sm)[33]) {
    int tx = threadIdx.x & 31, ty = threadIdx.x >> 5;
#pragma unroll
    for (int j = 0; j < 4; j++)
        sm[ty + 8 * j][tx] = W[(size_t)(k0 + ty + 8 * j) * N + n0 + tx];
    __syncthreads();
#pragma unroll
    for (int j = 0; j < 4; j++) {
        int r = ty + 8 * j;
        float v = sm[tx][r];
        __nv_bfloat16 hi, lo; split_bf16(v, hi, lo);
        size_t o = (size_t)(n0 + r) * K + k0 + tx;
        oh[o] = hi; ol[o] = lo;
    }
}

__global__ void convert_all_kernel(const float* __restrict__ x,
                                   const float* __restrict__ w1,
                                   const float* __restrict__ w2,
                                   const float* __restrict__ w3) {
    __shared__ float sm[32][33];
    int b = blockIdx.x;
    if (b < 8192) {
        size_t i = (size_t)b * 256 + threadIdx.x;
        float4 v = reinterpret_cast<const float4*>(x)[i];
        __nv_bfloat16 h0, h1, h2, h3, l0, l1, l2, l3;
        split_bf16(v.x, h0, l0); split_bf16(v.y, h1, l1);
        split_bf16(v.z, h2, l2); split_bf16(v.w, h3, l3);
        __nv_bfloat162* ph = reinterpret_cast<__nv_bfloat162*>(g_xh) + 2 * i;
        __nv_bfloat162* pl = reinterpret_cast<__nv_bfloat162*>(g_xl) + 2 * i;
        __nv_bfloat162 a; a.x = h0; a.y = h1; ph[0] = a;
        __nv_bfloat162 bb; bb.x = h2; bb.y = h3; ph[1] = bb;
        __nv_bfloat162 c; c.x = l0; c.y = l1; pl[0] = c;
        __nv_bfloat162 d; d.x = l2; d.y = l3; pl[1] = d;
    } else if (b < 8192 + 2048) {
        int t2 = b - 8192;
        int e = t2 >> 8, r = t2 & 255;
        int bx = r & 7, by = r >> 3;
        transpose_tile(w1 + (size_t)e * HID * RNK,
                       g_w1h + (size_t)e * RNK * HID,
                       g_w1l + (size_t)e * RNK * HID,
                       HID, RNK, by * 32, bx * 32, sm);
    } else if (b < 8192 + 2048 + 8192) {
        int t2 = b - 10240;
        int bx = t2 & 127, by = t2 >> 7;
        transpose_tile(w2, g_w2h, g_w2l, ERK, FFN, by * 32, bx * 32, sm);
    } else {
        int t2 = b - 18432;
        int bx = t2 & 31, by = t2 >> 5;
        transpose_tile(w3, g_w3h, g_w3l, FFN, HID, by * 32, bx * 32, sm);
    }
}

// ---------------------------------------------------------------------------
// Gather-GEMM, 128x256 CTA tile, 512 threads (16 warps), warp tile 32x64.
// 3-stage cp.async pipeline + 3-slot rotating B-fragment buffer.
// MODE 1: t = (x @ w1[e]) * mw   (grid 1 x MAXT1)
// MODE 2: h = gelu(t @ w2slice)  (grid 16 x MAXT2, K=512 pair-gathered)
// MODE 3: out = h @ lin2 + b     (grid 4 x 64, dense)
// ---------------------------------------------------------------------------
template <int MODE>
__global__ void __launch_bounds__(NTHREADS, 1)
mma_gemm(const float* __restrict__ bias, float* __restrict__ Cf) {
    __shared__ int ts[128];
    __shared__ float smw[128];
    extern __shared__ char smem[];
    const uint32_t sbase = s2u(smem);
    const int tid = threadIdx.x;
    const int lane = tid & 31;
    const int wid = tid >> 5;
    const int wm = wid & 3;           // 4 warps over M (32 rows each)
    const int wn = wid >> 2;          // 4 warps over N (64 cols each)

    int nrows = 128;
    int e = 0, e0 = 0, e1 = 0;
    if (MODE == 1) {
        if ((int)blockIdx.y >= g_meta[0]) return;
        e = g_t1grp[blockIdx.y];
        int r0 = g_t1row[blockIdx.y];
        nrows = min(128, g_ecnt[e] - r0);
        if (tid < 128) {
            int idx = g_eoff[e] + r0 + ((tid < nrows) ? tid : 0);
            int tk = g_etok[idx];
            ts[tid] = tk;
            smw[tid] = g_mw[tk * NE + e];
        }
    } else if (MODE == 2) {
        if ((int)blockIdx.y >= g_meta[1]) return;
        int p = g_t2grp[blockIdx.y];
        int r0 = g_t2row[blockIdx.y];
        nrows = min(128, g_pcnt[p] - r0);
        e0 = g_pe0[p]; e1 = g_pe1[p];
        if (tid < 128)
            ts[tid] = g_ptok[g_poff[p] + r0 + ((tid < nrows) ? tid : 0)];
    } else {
        if (tid < 128) ts[tid] = blockIdx.y * 128 + tid;
    }
    __syncthreads();

    const __nv_bfloat16 *Ahp, *Alp, *Bhp, *Blp;
    int ldA, ldB, brow0, NC;
    if (MODE == 1) {
        Ahp = g_xh; Alp = g_xl; ldA = HID;
        Bhp = g_w1h; Blp = g_w1l; ldB = HID;
        brow0 = e * 256;
        NC = HID / 32;
    } else if (MODE == 2) {
        Ahp = g_th; Alp = g_tl; ldA = ERK;
        Bhp = g_w2h; Blp = g_w2l; ldB = ERK;
        brow0 = blockIdx.x * 256;
        NC = 512 / 32;
    } else {
        Ahp = g_hh; Alp = g_hl; ldA = FFN;
        Bhp = g_w3h; Blp = g_w3l; ldB = FFN;
        brow0 = blockIdx.x * 256;
        NC = FFN / 32;
    }

    const int r0s = tid >> 2, q0 = tid & 3;          // r0s 0..127
    const size_t aoff0 = (size_t)ts[r0s] * ldA + q0 * 8;
    const size_t boff0 = (size_t)(brow0 + r0s) * ldB + q0 * 8;
    const size_t boff1 = (size_t)(brow0 + r0s + 128) * ldB + q0 * 8;

    const __nv_bfloat16 *pAh = Ahp + aoff0, *pAl = Alp + aoff0;
    const __nv_bfloat16 *pB0h = Bhp + boff0, *pB0l = Blp + boff0;
    const __nv_bfloat16 *pB1h = Bhp + boff1, *pB1l = Blp + boff1;
    const uint32_t dA  = (uint32_t)(r0s * ROWB + q0 * 16);
    const uint32_t dB0 = (uint32_t)(2 * A_T + r0s * ROWB + q0 * 16);
    const uint32_t dB1 = dB0 + (uint32_t)(128 * ROWB);

    float acc[2][8][4];
#pragma unroll
    for (int i = 0; i < 2; i++)
#pragma unroll
        for (int j = 0; j < 8; j++)
#pragma unroll
            for (int k = 0; k < 4; k++) acc[i][j][k] = 0.f;

    auto kseg = [&](int c) -> size_t {
        if (MODE == 2)
            return (c < 8) ? (size_t)e0 * 256 + (size_t)c * 32
                           : (size_t)e1 * 256 + (size_t)(c - 8) * 32;
        return (size_t)c * 32;
    };

    auto load_chunk = [&](int c, int st) {
        const size_t ko = kseg(c);
        const uint32_t s = sbase + (uint32_t)st * STG;
        cp16(s + dA,        pAh + ko);
        cp16(s + dA + A_T,  pAl + ko);
        cp16(s + dB0,       pB0h + ko);
        cp16(s + dB0 + B_T, pB0l + ko);
        cp16(s + dB1,       pB1h + ko);
        cp16(s + dB1 + B_T, pB1l + ko);
        cp_commit();
    };

    // 3-stage prologue: chunks 0 and 1 in flight
    load_chunk(0, 0);
    load_chunk(1, 1);

    const int g = lane >> 3, lr = lane & 7;
    int aofs[2], bofs[4];
#pragma unroll
    for (int mt = 0; mt < 2; mt++)
        aofs[mt] = (wm * 32 + mt * 16 + (g & 1) * 8 + lr) * ROWB + (g >> 1) * 16;
#pragma unroll
    for (int np = 0; np < 4; np++)
        bofs[np] = (wn * 64 + np * 16 + (g >> 1) * 8 + lr) * ROWB + (g & 1) * 16;

    int st = 0;   // stage index = c % 3
    for (int c = 0; c < NC; c++) {
        if (c + 1 < NC) cp_wait<1>(); else cp_wait<0>();
        __syncthreads();
        const uint32_t sA = sbase + (uint32_t)st * STG;
        const uint32_t sB = sA + (uint32_t)(2 * A_T);
        const bool have_next2 = (c + 2 < NC);

        uint32_t afh[2][4], afl[2][4];
        uint32_t bfh[3][4], bfl[3][4];
#pragma unroll
        for (int mt = 0; mt < 2; mt++) {
            ldsm4(afh[mt], sA + aofs[mt]);
            ldsm4(afl[mt], sA + aofs[mt] + A_T);
        }
        ldsm4(bfh[0], sB + bofs[0]);
        ldsm4(bfl[0], sB + bofs[0] + B_T);

#pragma unroll
        for (int ks = 0; ks < 2; ks++) {
#pragma unroll
            for (int np = 0; np < 4; np++) {
                const int j = ks * 4 + np;
                const int cs = j % 3, ns = (j + 1) % 3;
                if (np < 3) {
                    ldsm4(bfh[ns], sB + bofs[np + 1] + ks * 32);
                    ldsm4(bfl[ns], sB + bofs[np + 1] + ks * 32 + B_T);
                } else if (ks == 0) {
                    ldsm4(bfh[ns], sB + bofs[0] + 32);
                    ldsm4(bfl[ns], sB + bofs[0] + 32 + B_T);
                }
#pragma unroll
                for (int mt = 0; mt < 2; mt++) {
#pragma unroll
                    for (int h2 = 0; h2 < 2; h2++) {
                        float* cc = acc[mt][np * 2 + h2];
                        mma16816(cc, afh[mt], bfh[cs] + h2 * 2);
                        mma16816(cc, afh[mt], bfl[cs] + h2 * 2);
                        mma16816(cc, afl[mt], bfh[cs] + h2 * 2);
                    }
                }
                // issue chunk c+2 after first MMA group
                if (ks == 0 && np == 0 && have_next2) {
                    int st2 = st + 2; if (st2 >= 3) st2 -= 3;
                    load_chunk(c + 2, st2);
                }
            }
            if (ks == 0) {
#pragma unroll
                for (int mt = 0; mt < 2; mt++) {
                    ldsm4(afh[mt], sA + aofs[mt] + 32);
                    ldsm4(afl[mt], sA + aofs[mt] + 32 + A_T);
                }
            }
        }
        if (++st == 3) st = 0;
    }

    // Epilogue
#pragma unroll
    for (int mt = 0; mt < 2; mt++) {
#pragma unroll
        for (int half = 0; half < 2; half++) {
            const int rl = wm * 32 + mt * 16 + half * 8 + (lane >> 2);
            const bool valid = rl < nrows;
            const int tok = ts[rl];
            float s = 1.f;
            if (MODE == 1) s = smw[rl];
            size_t rbase;
            if (MODE == 1)      rbase = (size_t)tok * ERK + e * 256;
            else if (MODE == 2) rbase = (size_t)tok * FFN + blockIdx.x * 256;
            else                rbase = (size_t)tok * HID + blockIdx.x * 256;
#pragma unroll
            for (int nt = 0; nt < 8; nt++) {
                const int col = wn * 64 + nt * 8 + (lane & 3) * 2;
                float v0 = acc[mt][nt][half * 2 + 0];
                float v1 = acc[mt][nt][half * 2 + 1];
                if (MODE == 3) {
                    if (valid) {
                        float2 o;
                        o.x = v0 + bias[blockIdx.x * 256 + col];
                        o.y = v1 + bias[blockIdx.x * 256 + col + 1];
                        *reinterpret_cast<float2*>(Cf + rbase + col) = o;
                    }
                } else {
                    if (MODE == 1) { v0 *= s; v1 *= s; }
                    else {
                        v0 = 0.5f * v0 * (1.f + erff(v0 * 0.70710678118654752f));
                        v1 = 0.5f * v1 * (1.f + erff(v1 * 0.70710678118654752f));
                    }
                    if (valid) {
                        __nv_bfloat16 h0, h1, l0, l1;
                        split_bf16(v0, h0, l0); split_bf16(v1, h1, l1);
                        __nv_bfloat162 hp; hp.x = h0; hp.y = h1;
                        __nv_bfloat162 lp; lp.x = l0; lp.y = l1;
                        __nv_bfloat16* Ch = (MODE == 1) ? g_th : g_hh;
                        __nv_bfloat16* Cl = (MODE == 1) ? g_tl : g_hl;
                        *reinterpret_cast<__nv_bfloat162*>(Ch + rbase + col) = hp;
                        *reinterpret_cast<__nv_bfloat162*>(Cl + rbase + col) = lp;
                    }
                }
            }
        }
    }
}

// ---------------------------------------------------------------------------
extern "C" void kernel_launch(void* const* d_in, const int* in_sizes, int n_in,
                              void* d_out, int out_size) {
    const float* x        = (const float*)d_in[0];
    const float* router_w = (const float*)d_in[1];
    const float* router_b = (const float*)d_in[2];
    const float* w1       = (const float*)d_in[3];
    const float* w2       = (const float*)d_in[4];
    const float* lin2_w   = (const float*)d_in[5];
    const float* lin2_b   = (const float*)d_in[6];
    float* out = (float*)d_out;

    cudaFuncSetAttribute(mma_gemm<1>, cudaFuncAttributeMaxDynamicSharedMemorySize, SMEM_BYTES);
    cudaFuncSetAttribute(mma_gemm<2>, cudaFuncAttributeMaxDynamicSharedMemorySize, SMEM_BYTES);
    cudaFuncSetAttribute(mma_gemm<3>, cudaFuncAttributeMaxDynamicSharedMemorySize, SMEM_BYTES);

    zero_kernel<<<1, 32>>>();                                       // 0
    router_kernel<<<TOK / 8, 256>>>(x, router_w, router_b);         // 1
    scatter_kernel<<<TOK / 256, 256>>>();                           // 2 (plan integrated)
    convert_all_kernel<<<22528, 256>>>(x, w1, w2, lin2_w);          // 3

    // Stage 1 (sparse, per-expert, N=256): t = (x @ w1[e]) * mw
    mma_gemm<1><<<dim3(1, MAXT1), NTHREADS, SMEM_BYTES>>>(nullptr, nullptr);          // 4
    // Stage 2 (sparse, per-pair, K=512): h = gelu(t @ w2)
    mma_gemm<2><<<dim3(FFN / 256, MAXT2), NTHREADS, SMEM_BYTES>>>(nullptr, nullptr);  // 5
    // Stage 3 (dense): out = h @ lin2 + b
    mma_gemm<3><<<dim3(HID / 256, TOK / 128), NTHREADS, SMEM_BYTES>>>(lin2_b, out);   // 6
}

// round 15
// speedup vs baseline: 1.0203x; 1.0203x over previous
#include <cuda_runtime.h>
#include <cuda_bf16.h>
#include <stdint.h>
#include <math.h>

#define TOK 8192
#define HID 1024
#define RNK 256
#define FFN 4096
#define NE  8
#define ERK (NE*RNK)  // 2048
#define NPAIR 28
#define MAXT1 136
#define MAXT2 92

#define NTHREADS 512
#define ROWB 80
#define A_T (128*ROWB)            // 10240
#define B_T (256*ROWB)            // 20480
#define STG (2*A_T + 2*B_T)       // 61440
#define SMEM_BYTES (2*STG)        // 122880 (2-stage: best measured config)

// ---------------------------------------------------------------------------
// Scratch (device globals)
// ---------------------------------------------------------------------------
__device__ float g_mw[TOK * NE];
__device__ int g_e0t[TOK], g_e1t[TOK], g_pidt[TOK];
__device__ int g_pcnt[NPAIR], g_poff[NPAIR], g_pfill[NPAIR], g_ptok[TOK];
__device__ int g_ecnt[NE], g_eoff[NE], g_efill[NE], g_etok[2 * TOK];
__device__ int g_t1grp[MAXT1], g_t1row[MAXT1];
__device__ int g_t2grp[MAXT2], g_t2row[MAXT2];
__device__ int g_pe0[NPAIR], g_pe1[NPAIR];
__device__ int g_meta[2];

__device__ __nv_bfloat16 g_xh[(size_t)TOK * HID], g_xl[(size_t)TOK * HID];
__device__ __nv_bfloat16 g_th[(size_t)TOK * ERK], g_tl[(size_t)TOK * ERK];
__device__ __nv_bfloat16 g_hh[(size_t)TOK * FFN], g_hl[(size_t)TOK * FFN];
__device__ __nv_bfloat16 g_w1h[(size_t)ERK * HID], g_w1l[(size_t)ERK * HID];
__device__ __nv_bfloat16 g_w2h[(size_t)FFN * ERK], g_w2l[(size_t)FFN * ERK];
__device__ __nv_bfloat16 g_w3h[(size_t)HID * FFN], g_w3l[(size_t)HID * FFN];

// ---------------------------------------------------------------------------
// PTX helpers (base sm_103 target)
// ---------------------------------------------------------------------------
__device__ __forceinline__ uint32_t s2u(const void* p) {
    uint32_t a;
    asm("{ .reg .u64 t; cvta.to.shared.u64 t, %1; cvt.u32.u64 %0, t; }" : "=r"(a) : "l"(p));
    return a;
}
__device__ __forceinline__ void cp16(uint32_t dst, const void* src) {
    asm volatile("cp.async.cg.shared.global [%0], [%1], 16;" :: "r"(dst), "l"(src) : "memory");
}
__device__ __forceinline__ void cp_commit() {
    asm volatile("cp.async.commit_group;" ::: "memory");
}
template <int N>
__device__ __forceinline__ void cp_wait() {
    asm volatile("cp.async.wait_group %0;" :: "n"(N) : "memory");
}
__device__ __forceinline__ void ldsm4(uint32_t* r, uint32_t addr) {
    asm volatile("ldmatrix.sync.aligned.m8n8.x4.shared.b16 {%0,%1,%2,%3}, [%4];"
                 : "=r"(r[0]), "=r"(r[1]), "=r"(r[2]), "=r"(r[3]) : "r"(addr));
}
__device__ __forceinline__ void mma16816(float* c, const uint32_t* a, const uint32_t* b) {
    asm volatile(
        "mma.sync.aligned.m16n8k16.row.col.f32.bf16.bf16.f32 "
        "{%0,%1,%2,%3}, {%4,%5,%6,%7}, {%8,%9}, {%0,%1,%2,%3};"
        : "+f"(c[0]), "+f"(c[1]), "+f"(c[2]), "+f"(c[3])
        : "r"(a[0]), "r"(a[1]), "r"(a[2]), "r"(a[3]), "r"(b[0]), "r"(b[1]));
}
__device__ __forceinline__ void split_bf16(float v, __nv_bfloat16& hi, __nv_bfloat16& lo) {
    hi = __float2bfloat16(v);
    lo = __float2bfloat16(v - __bfloat162float(hi));
}

// ---------------------------------------------------------------------------
// Routing infrastructure
// ---------------------------------------------------------------------------
__global__ void zero_kernel() {
    int i = threadIdx.x;
    if (i < NPAIR) { g_pcnt[i] = 0; g_pfill[i] = 0; }
    if (i < NE)    { g_ecnt[i] = 0; g_efill[i] = 0; }
}

__global__ void router_kernel(const float* __restrict__ x,
                              const float* __restrict__ rw,
                              const float* __restrict__ rb) {
    int warp = (blockIdx.x * blockDim.x + threadIdx.x) >> 5;
    int lane = threadIdx.x & 31;
    if (warp >= TOK) return;

    const float4* xr = reinterpret_cast<const float4*>(x + (size_t)warp * HID);
    float acc[NE];
#pragma unroll
    for (int e = 0; e < NE; e++) acc[e] = 0.f;

    for (int i = lane; i < HID / 4; i += 32) {
        float4 xv = xr[i];
        int h = i * 4;
        const float4* w0 = reinterpret_cast<const float4*>(rw + (size_t)h * NE);
        float4 a0 = w0[0], a1 = w0[1];
        float4 b0 = w0[2], b1 = w0[3];
        float4 c0 = w0[4], c1 = w0[5];
        float4 d0 = w0[6], d1 = w0[7];
        acc[0] += xv.x*a0.x + xv.y*b0.x + xv.z*c0.x + xv.w*d0.x;
        acc[1] += xv.x*a0.y + xv.y*b0.y + xv.z*c0.y + xv.w*d0.y;
        acc[2] += xv.x*a0.z + xv.y*b0.z + xv.z*c0.z + xv.w*d0.z;
        acc[3] += xv.x*a0.w + xv.y*b0.w + xv.z*c0.w + xv.w*d0.w;
        acc[4] += xv.x*a1.x + xv.y*b1.x + xv.z*c1.x + xv.w*d1.x;
        acc[5] += xv.x*a1.y + xv.y*b1.y + xv.z*c1.y + xv.w*d1.y;
        acc[6] += xv.x*a1.z + xv.y*b1.z + xv.z*c1.z + xv.w*d1.z;
        acc[7] += xv.x*a1.w + xv.y*b1.w + xv.z*c1.w + xv.w*d1.w;
    }
#pragma unroll
    for (int e = 0; e < NE; e++) {
#pragma unroll
        for (int o = 16; o > 0; o >>= 1)
            acc[e] += __shfl_xor_sync(0xffffffffu, acc[e], o);
    }
    if (lane == 0) {
        float lg[NE], m = -1e30f;
#pragma unroll
        for (int e = 0; e < NE; e++) { lg[e] = acc[e] + rb[e]; m = fmaxf(m, lg[e]); }
        float p[NE], s = 0.f;
#pragma unroll
        for (int e = 0; e < NE; e++) { p[e] = expf(lg[e] - m); s += p[e]; }
        float inv = 1.f / s;
        int i0 = 0;
#pragma unroll
        for (int e = 1; e < NE; e++) if (p[e] > p[i0]) i0 = e;
        int i1 = (i0 == 0) ? 1 : 0;
#pragma unroll
        for (int e = 0; e < NE; e++) { if (e == i0) continue; if (p[e] > p[i1]) i1 = e; }
#pragma unroll
        for (int e = 0; e < NE; e++)
            g_mw[warp * NE + e] = (e == i0 || e == i1) ? p[e] * inv : 0.f;
        int e0 = min(i0, i1), e1 = max(i0, i1);
        int pid = e0 * (2 * NE - e0 - 1) / 2 + (e1 - e0 - 1);
        g_e0t[warp] = e0; g_e1t[warp] = e1; g_pidt[warp] = pid;
        atomicAdd(&g_pcnt[pid], 1);
        atomicAdd(&g_ecnt[e0], 1);
        atomicAdd(&g_ecnt[e1], 1);
    }
}

// scatter + integrated planning
__global__ void scatter_kernel() {
    __shared__ int s_eoff[NE], s_poff[NPAIR];
    if (threadIdx.x == 0) {
        int off = 0;
#pragma unroll
        for (int e2 = 0; e2 < NE; e2++) { s_eoff[e2] = off; off += g_ecnt[e2]; }
        off = 0;
#pragma unroll
        for (int p = 0; p < NPAIR; p++) { s_poff[p] = off; off += g_pcnt[p]; }
    }
    __syncthreads();

    if (blockIdx.x == 0 && threadIdx.x == 0) {
        int nt = 0;
        for (int e2 = 0; e2 < NE; e2++) {
            g_eoff[e2] = s_eoff[e2];
            for (int r = 0; r < g_ecnt[e2]; r += 128) { g_t1grp[nt] = e2; g_t1row[nt] = r; nt++; }
        }
        g_meta[0] = nt;
        nt = 0;
        int p = 0;
        for (int a = 0; a < NE; a++)
            for (int b = a + 1; b < NE; b++) {
                g_pe0[p] = a; g_pe1[p] = b; g_poff[p] = s_poff[p];
                for (int r = 0; r < g_pcnt[p]; r += 128) { g_t2grp[nt] = p; g_t2row[nt] = r; nt++; }
                p++;
            }
        g_meta[1] = nt;
    }

    int t = blockIdx.x * blockDim.x + threadIdx.x;
    if (t >= TOK) return;
    int pid = g_pidt[t];
    int pos = atomicAdd(&g_pfill[pid], 1);
    g_ptok[s_poff[pid] + pos] = t;
    int e0 = g_e0t[t], e1 = g_e1t[t];
    pos = atomicAdd(&g_efill[e0], 1); g_etok[s_eoff[e0] + pos] = t;
    pos = atomicAdd(&g_efill[e1], 1); g_etok[s_eoff[e1] + pos] = t;
}

// ---------------------------------------------------------------------------
// Fused conversion. Transposes use 64x32 tiles: 16B/thread uint4 stores ->
// 128B coalesced segments per output row (vs 64B before).
// grid = 8192 (x) + 1024 (w1) + 4096 (w2) + 2048 (w3) = 15360, block 256
// ---------------------------------------------------------------------------
__device__ __forceinline__ void transpose_tile64(const float* __restrict__ W,
                                                 __nv_bfloat16* __restrict__ oh,
                                                 __nv_bfloat16* __restrict__ ol,
                                                 int K, int N, int k0, int n0,
                                                 float (*sm)[33]) {
    int c = threadIdx.x & 31, r0 = threadIdx.x >> 5;   // 32 cols x 8 rows
#pragma unroll
    for (int j = 0; j < 8; j++)
        sm[r0 + 8 * j][c] = W[(size_t)(k0 + r0 + 8 * j) * N + n0 + c];
    __syncthreads();
    int n = threadIdx.x >> 3, k8 = (threadIdx.x & 7) * 8;  // 32 n x 8 k-groups
    __nv_bfloat16 h8[8], l8[8];
#pragma unroll
    for (int i = 0; i < 8; i++) split_bf16(sm[k8 + i][n], h8[i], l8[i]);
    size_t o = (size_t)(n0 + n) * K + k0 + k8;
    *reinterpret_cast<uint4*>(oh + o) = *reinterpret_cast<uint4*>(h8);
    *reinterpret_cast<uint4*>(ol + o) = *reinterpret_cast<uint4*>(l8);
}

__global__ void convert_all_kernel(const float* __restrict__ x,
                                   const float* __restrict__ w1,
                                   const float* __restrict__ w2,
                                   const float* __restrict__ w3) {
    __shared__ float sm[64][33];
    int b = blockIdx.x;
    if (b < 8192) {
        size_t i = (size_t)b * 256 + threadIdx.x;
        float4 v = reinterpret_cast<const float4*>(x)[i];
        __nv_bfloat16 h0, h1, h2, h3, l0, l1, l2, l3;
        split_bf16(v.x, h0, l0); split_bf16(v.y, h1, l1);
        split_bf16(v.z, h2, l2); split_bf16(v.w, h3, l3);
        __nv_bfloat162* ph = reinterpret_cast<__nv_bfloat162*>(g_xh) + 2 * i;
        __nv_bfloat162* pl = reinterpret_cast<__nv_bfloat162*>(g_xl) + 2 * i;
        __nv_bfloat162 a; a.x = h0; a.y = h1; ph[0] = a;
        __nv_bfloat162 bb; bb.x = h2; bb.y = h3; ph[1] = bb;
        __nv_bfloat162 c; c.x = l0; c.y = l1; pl[0] = c;
        __nv_bfloat162 d; d.x = l2; d.y = l3; pl[1] = d;
    } else if (b < 8192 + 1024) {
        int t2 = b - 8192;                 // per expert: 16 k-tiles x 8 n-tiles
        int e = t2 >> 7, r = t2 & 127;
        int bx = r & 7, by = r >> 3;
        transpose_tile64(w1 + (size_t)e * HID * RNK,
                         g_w1h + (size_t)e * RNK * HID,
                         g_w1l + (size_t)e * RNK * HID,
                         HID, RNK, by * 64, bx * 32, sm);
    } else if (b < 8192 + 1024 + 4096) {
        int t2 = b - 9216;                 // 32 k-tiles x 128 n-tiles
        int bx = t2 & 127, by = t2 >> 7;
        transpose_tile64(w2, g_w2h, g_w2l, ERK, FFN, by * 64, bx * 32, sm);
    } else {
        int t2 = b - 13312;                // 64 k-tiles x 32 n-tiles
        int bx = t2 & 31, by = t2 >> 5;
        transpose_tile64(w3, g_w3h, g_w3l, FFN, HID, by * 64, bx * 32, sm);
    }
}

// ---------------------------------------------------------------------------
// Gather-GEMM, 128x256 CTA tile, 512 threads (16 warps), warp tile 32x64.
// 2-stage cp.async pipeline (best measured) + 3-slot rotating B fragments.
// MODE 1: t = (x @ w1[e]) * mw   (grid 1 x MAXT1)
// MODE 2: h = gelu(t @ w2slice)  (grid 16 x MAXT2, K=512 pair-gathered)
// MODE 3: out = h @ lin2 + b     (grid 4 x 64, dense)
// ---------------------------------------------------------------------------
template <int MODE>
__global__ void __launch_bounds__(NTHREADS, 1)
mma_gemm(const float* __restrict__ bias, float* __restrict__ Cf) {
    __shared__ int ts[128];
    __shared__ float smw[128];
    extern __shared__ char smem[];
    const uint32_t sbase = s2u(smem);
    const int tid = threadIdx.x;
    const int lane = tid & 31;
    const int wid = tid >> 5;
    const int wm = wid & 3;           // 4 warps over M (32 rows each)
    const int wn = wid >> 2;          // 4 warps over N (64 cols each)

    int nrows = 128;
    int e = 0, e0 = 0, e1 = 0;
    if (MODE == 1) {
        if ((int)blockIdx.y >= g_meta[0]) return;
        e = g_t1grp[blockIdx.y];
        int r0 = g_t1row[blockIdx.y];
        nrows = min(128, g_ecnt[e] - r0);
        if (tid < 128) {
            int idx = g_eoff[e] + r0 + ((tid < nrows) ? tid : 0);
            int tk = g_etok[idx];
            ts[tid] = tk;
            smw[tid] = g_mw[tk * NE + e];
        }
    } else if (MODE == 2) {
        if ((int)blockIdx.y >= g_meta[1]) return;
        int p = g_t2grp[blockIdx.y];
        int r0 = g_t2row[blockIdx.y];
        nrows = min(128, g_pcnt[p] - r0);
        e0 = g_pe0[p]; e1 = g_pe1[p];
        if (tid < 128)
            ts[tid] = g_ptok[g_poff[p] + r0 + ((tid < nrows) ? tid : 0)];
    } else {
        if (tid < 128) ts[tid] = blockIdx.y * 128 + tid;
    }
    __syncthreads();

    const __nv_bfloat16 *Ahp, *Alp, *Bhp, *Blp;
    int ldA, ldB, brow0, NC;
    if (MODE == 1) {
        Ahp = g_xh; Alp = g_xl; ldA = HID;
        Bhp = g_w1h; Blp = g_w1l; ldB = HID;
        brow0 = e * 256;
        NC = HID / 32;
    } else if (MODE == 2) {
        Ahp = g_th; Alp = g_tl; ldA = ERK;
        Bhp = g_w2h; Blp = g_w2l; ldB = ERK;
        brow0 = blockIdx.x * 256;
        NC = 512 / 32;
    } else {
        Ahp = g_hh; Alp = g_hl; ldA = FFN;
        Bhp = g_w3h; Blp = g_w3l; ldB = FFN;
        brow0 = blockIdx.x * 256;
        NC = FFN / 32;
    }

    const int r0s = tid >> 2, q0 = tid & 3;          // r0s 0..127
    const size_t aoff0 = (size_t)ts[r0s] * ldA + q0 * 8;
    const size_t boff0 = (size_t)(brow0 + r0s) * ldB + q0 * 8;
    const size_t boff1 = (size_t)(brow0 + r0s + 128) * ldB + q0 * 8;

    const __nv_bfloat16 *pAh = Ahp + aoff0, *pAl = Alp + aoff0;
    const __nv_bfloat16 *pB0h = Bhp + boff0, *pB0l = Blp + boff0;
    const __nv_bfloat16 *pB1h = Bhp + boff1, *pB1l = Blp + boff1;
    const uint32_t dA  = (uint32_t)(r0s * ROWB + q0 * 16);
    const uint32_t dB0 = (uint32_t)(2 * A_T + r0s * ROWB + q0 * 16);
    const uint32_t dB1 = dB0 + (uint32_t)(128 * ROWB);

    float acc[2][8][4];
#pragma unroll
    for (int i = 0; i < 2; i++)
#pragma unroll
        for (int j = 0; j < 8; j++)
#pragma unroll
            for (int k = 0; k < 4; k++) acc[i][j][k] = 0.f;

    auto kseg = [&](int c) -> size_t {
        if (MODE == 2)
            return (c < 8) ? (size_t)e0 * 256 + (size_t)c * 32
                           : (size_t)e1 * 256 + (size_t)(c - 8) * 32;
        return (size_t)c * 32;
    };

    auto load_chunk = [&](int c, int st) {
        const size_t ko = kseg(c);
        const uint32_t s = sbase + (uint32_t)st * STG;
        cp16(s + dA,        pAh + ko);
        cp16(s + dA + A_T,  pAl + ko);
        cp16(s + dB0,       pB0h + ko);
        cp16(s + dB0 + B_T, pB0l + ko);
        cp16(s + dB1,       pB1h + ko);
        cp16(s + dB1 + B_T, pB1l + ko);
        cp_commit();
    };

    load_chunk(0, 0);

    const int g = lane >> 3, lr = lane & 7;
    int aofs[2], bofs[4];
#pragma unroll
    for (int mt = 0; mt < 2; mt++)
        aofs[mt] = (wm * 32 + mt * 16 + (g & 1) * 8 + lr) * ROWB + (g >> 1) * 16;
#pragma unroll
    for (int np = 0; np < 4; np++)
        bofs[np] = (wn * 64 + np * 16 + (g >> 1) * 8 + lr) * ROWB + (g & 1) * 16;

    for (int c = 0; c < NC; c++) {
        cp_wait<0>();
        __syncthreads();
        const uint32_t sA = sbase + (uint32_t)((c & 1) * STG);
        const uint32_t sB = sA + (uint32_t)(2 * A_T);
        const bool have_next = (c + 1 < NC);

        uint32_t afh[2][4], afl[2][4];
        uint32_t bfh[3][4], bfl[3][4];
#pragma unroll
        for (int mt = 0; mt < 2; mt++) {
            ldsm4(afh[mt], sA + aofs[mt]);
            ldsm4(afl[mt], sA + aofs[mt] + A_T);
        }
        ldsm4(bfh[0], sB + bofs[0]);
        ldsm4(bfl[0], sB + bofs[0] + B_T);

#pragma unroll
        for (int ks = 0; ks < 2; ks++) {
#pragma unroll
            for (int np = 0; np < 4; np++) {
                const int j = ks * 4 + np;
                const int cs = j % 3, ns = (j + 1) % 3;
                if (np < 3) {
                    ldsm4(bfh[ns], sB + bofs[np + 1] + ks * 32);
                    ldsm4(bfl[ns], sB + bofs[np + 1] + ks * 32 + B_T);
                } else if (ks == 0) {
                    ldsm4(bfh[ns], sB + bofs[0] + 32);
                    ldsm4(bfl[ns], sB + bofs[0] + 32 + B_T);
                }
#pragma unroll
                for (int mt = 0; mt < 2; mt++) {
#pragma unroll
                    for (int h2 = 0; h2 < 2; h2++) {
                        float* cc = acc[mt][np * 2 + h2];
                        mma16816(cc, afh[mt], bfh[cs] + h2 * 2);
                        mma16816(cc, afh[mt], bfl[cs] + h2 * 2);
                        mma16816(cc, afl[mt], bfh[cs] + h2 * 2);
                    }
                }
                if (ks == 0 && np == 0 && have_next) load_chunk(c + 1, (c + 1) & 1);
            }
            if (ks == 0) {
#pragma unroll
                for (int mt = 0; mt < 2; mt++) {
                    ldsm4(afh[mt], sA + aofs[mt] + 32);
                    ldsm4(afl[mt], sA + aofs[mt] + 32 + A_T);
                }
            }
        }
    }

    // Epilogue
#pragma unroll
    for (int mt = 0; mt < 2; mt++) {
#pragma unroll
        for (int half = 0; half < 2; half++) {
            const int rl = wm * 32 + mt * 16 + half * 8 + (lane >> 2);
            const bool valid = rl < nrows;
            const int tok = ts[rl];
            float s = 1.f;
            if (MODE == 1) s = smw[rl];
            size_t rbase;
            if (MODE == 1)      rbase = (size_t)tok * ERK + e * 256;
            else if (MODE == 2) rbase = (size_t)tok * FFN + blockIdx.x * 256;
            else                rbase = (size_t)tok * HID + blockIdx.x * 256;
#pragma unroll
            for (int nt = 0; nt < 8; nt++) {
                const int col = wn * 64 + nt * 8 + (lane & 3) * 2;
                float v0 = acc[mt][nt][half * 2 + 0];
                float v1 = acc[mt][nt][half * 2 + 1];
                if (MODE == 3) {
                    if (valid) {
                        float2 o;
                        o.x = v0 + bias[blockIdx.x * 256 + col];
                        o.y = v1 + bias[blockIdx.x * 256 + col + 1];
                        *reinterpret_cast<float2*>(Cf + rbase + col) = o;
                    }
                } else {
                    if (MODE == 1) { v0 *= s; v1 *= s; }
                    else {
                        v0 = 0.5f * v0 * (1.f + erff(v0 * 0.70710678118654752f));
                        v1 = 0.5f * v1 * (1.f + erff(v1 * 0.70710678118654752f));
                    }
                    if (valid) {
                        __nv_bfloat16 h0, h1, l0, l1;
                        split_bf16(v0, h0, l0); split_bf16(v1, h1, l1);
                        __nv_bfloat162 hp; hp.x = h0; hp.y = h1;
                        __nv_bfloat162 lp; lp.x = l0; lp.y = l1;
                        __nv_bfloat16* Ch = (MODE == 1) ? g_th : g_hh;
                        __nv_bfloat16* Cl = (MODE == 1) ? g_tl : g_hl;
                        *reinterpret_cast<__nv_bfloat162*>(Ch + rbase + col) = hp;
                        *reinterpret_cast<__nv_bfloat162*>(Cl + rbase + col) = lp;
                    }
                }
            }
        }
    }
}

// ---------------------------------------------------------------------------
extern "C" void kernel_launch(void* const* d_in, const int* in_sizes, int n_in,
                              void* d_out, int out_size) {
    const float* x        = (const float*)d_in[0];
    const float* router_w = (const float*)d_in[1];
    const float* router_b = (const float*)d_in[2];
    const float* w1       = (const float*)d_in[3];
    const float* w2       = (const float*)d_in[4];
    const float* lin2_w   = (const float*)d_in[5];
    const float* lin2_b   = (const float*)d_in[6];
    float* out = (float*)d_out;

    cudaFuncSetAttribute(mma_gemm<1>, cudaFuncAttributeMaxDynamicSharedMemorySize, SMEM_BYTES);
    cudaFuncSetAttribute(mma_gemm<2>, cudaFuncAttributeMaxDynamicSharedMemorySize, SMEM_BYTES);
    cudaFuncSetAttribute(mma_gemm<3>, cudaFuncAttributeMaxDynamicSharedMemorySize, SMEM_BYTES);

    zero_kernel<<<1, 32>>>();                                       // 0
    router_kernel<<<TOK / 8, 256>>>(x, router_w, router_b);         // 1
    scatter_kernel<<<TOK / 256, 256>>>();                           // 2 (plan integrated)
    convert_all_kernel<<<15360, 256>>>(x, w1, w2, lin2_w);          // 3

    // Stage 1 (sparse, per-expert, N=256): t = (x @ w1[e]) * mw
    mma_gemm<1><<<dim3(1, MAXT1), NTHREADS, SMEM_BYTES>>>(nullptr, nullptr);          // 4
    // Stage 2 (sparse, per-pair, K=512): h = gelu(t @ w2)
    mma_gemm<2><<<dim3(FFN / 256, MAXT2), NTHREADS, SMEM_BYTES>>>(nullptr, nullptr);  // 5
    // Stage 3 (dense): out = h @ lin2 + b
    mma_gemm<3><<<dim3(HID / 256, TOK / 128), NTHREADS, SMEM_BYTES>>>(lin2_b, out);   // 6
}

// round 16
// speedup vs baseline: 1.0254x; 1.0050x over previous
#include <cuda_runtime.h>
#include <cuda_bf16.h>
#include <stdint.h>
#include <math.h>

#define TOK 8192
#define HID 1024
#define RNK 256
#define FFN 4096
#define NE  8
#define ERK (NE*RNK)  // 2048
#define NPAIR 28
#define MAXT1 136
#define MAXT2 92

#define NTHREADS 512
#define ROWB 80
#define A_T (128*ROWB)            // 10240
#define B_T (256*ROWB)            // 20480
#define STG (2*A_T + 2*B_T)       // 61440
#define SMEM_BYTES (2*STG)        // 122880

// ---------------------------------------------------------------------------
// Scratch (device globals)
// ---------------------------------------------------------------------------
__device__ float g_mw[TOK * NE];
__device__ int g_e0t[TOK], g_e1t[TOK], g_pidt[TOK];
__device__ int g_pcnt[NPAIR], g_poff[NPAIR], g_pfill[NPAIR], g_ptok[TOK];
__device__ int g_ecnt[NE], g_eoff[NE], g_efill[NE], g_etok[2 * TOK];
__device__ int g_t1grp[MAXT1], g_t1row[MAXT1];
__device__ int g_t2grp[MAXT2], g_t2row[MAXT2];
__device__ int g_pe0[NPAIR], g_pe1[NPAIR];
__device__ int g_meta[2];

__device__ __nv_bfloat16 g_xh[(size_t)TOK * HID], g_xl[(size_t)TOK * HID];
__device__ __nv_bfloat16 g_th[(size_t)TOK * ERK], g_tl[(size_t)TOK * ERK];
__device__ __nv_bfloat16 g_hh[(size_t)TOK * FFN], g_hl[(size_t)TOK * FFN];
__device__ __nv_bfloat16 g_w1h[(size_t)ERK * HID], g_w1l[(size_t)ERK * HID];
__device__ __nv_bfloat16 g_w2h[(size_t)FFN * ERK], g_w2l[(size_t)FFN * ERK];
__device__ __nv_bfloat16 g_w3h[(size_t)HID * FFN], g_w3l[(size_t)HID * FFN];

// ---------------------------------------------------------------------------
// PTX helpers (base sm_103 target)
// ---------------------------------------------------------------------------
__device__ __forceinline__ uint32_t s2u(const void* p) {
    uint32_t a;
    asm("{ .reg .u64 t; cvta.to.shared.u64 t, %1; cvt.u32.u64 %0, t; }" : "=r"(a) : "l"(p));
    return a;
}
__device__ __forceinline__ void cp16(uint32_t dst, const void* src) {
    asm volatile("cp.async.cg.shared.global [%0], [%1], 16;" :: "r"(dst), "l"(src) : "memory");
}
__device__ __forceinline__ void cp_commit() {
    asm volatile("cp.async.commit_group;" ::: "memory");
}
template <int N>
__device__ __forceinline__ void cp_wait() {
    asm volatile("cp.async.wait_group %0;" :: "n"(N) : "memory");
}
__device__ __forceinline__ void ldsm4(uint32_t* r, uint32_t addr) {
    asm volatile("ldmatrix.sync.aligned.m8n8.x4.shared.b16 {%0,%1,%2,%3}, [%4];"
                 : "=r"(r[0]), "=r"(r[1]), "=r"(r[2]), "=r"(r[3]) : "r"(addr));
}
__device__ __forceinline__ void mma16816(float* c, const uint32_t* a, const uint32_t* b) {
    asm volatile(
        "mma.sync.aligned.m16n8k16.row.col.f32.bf16.bf16.f32 "
        "{%0,%1,%2,%3}, {%4,%5,%6,%7}, {%8,%9}, {%0,%1,%2,%3};"
        : "+f"(c[0]), "+f"(c[1]), "+f"(c[2]), "+f"(c[3])
        : "r"(a[0]), "r"(a[1]), "r"(a[2]), "r"(a[3]), "r"(b[0]), "r"(b[1]));
}
__device__ __forceinline__ void split_bf16(float v, __nv_bfloat16& hi, __nv_bfloat16& lo) {
    hi = __float2bfloat16(v);
    lo = __float2bfloat16(v - __bfloat162float(hi));
}

// ---------------------------------------------------------------------------
// Routing infrastructure
// ---------------------------------------------------------------------------
__global__ void zero_kernel() {
    int i = threadIdx.x;
    if (i < NPAIR) { g_pcnt[i] = 0; g_pfill[i] = 0; }
    if (i < NE)    { g_ecnt[i] = 0; g_efill[i] = 0; }
}

// scatter + integrated planning
__global__ void scatter_kernel() {
    __shared__ int s_eoff[NE], s_poff[NPAIR];
    if (threadIdx.x == 0) {
        int off = 0;
#pragma unroll
        for (int e2 = 0; e2 < NE; e2++) { s_eoff[e2] = off; off += g_ecnt[e2]; }
        off = 0;
#pragma unroll
        for (int p = 0; p < NPAIR; p++) { s_poff[p] = off; off += g_pcnt[p]; }
    }
    __syncthreads();

    if (blockIdx.x == 0 && threadIdx.x == 0) {
        int nt = 0;
        for (int e2 = 0; e2 < NE; e2++) {
            g_eoff[e2] = s_eoff[e2];
            for (int r = 0; r < g_ecnt[e2]; r += 128) { g_t1grp[nt] = e2; g_t1row[nt] = r; nt++; }
        }
        g_meta[0] = nt;
        nt = 0;
        int p = 0;
        for (int a = 0; a < NE; a++)
            for (int b = a + 1; b < NE; b++) {
                g_pe0[p] = a; g_pe1[p] = b; g_poff[p] = s_poff[p];
                for (int r = 0; r < g_pcnt[p]; r += 128) { g_t2grp[nt] = p; g_t2row[nt] = r; nt++; }
                p++;
            }
        g_meta[1] = nt;
    }

    int t = blockIdx.x * blockDim.x + threadIdx.x;
    if (t >= TOK) return;
    int pid = g_pidt[t];
    int pos = atomicAdd(&g_pfill[pid], 1);
    g_ptok[s_poff[pid] + pos] = t;
    int e0 = g_e0t[t], e1 = g_e1t[t];
    pos = atomicAdd(&g_efill[e0], 1); g_etok[s_eoff[e0] + pos] = t;
    pos = atomicAdd(&g_efill[e1], 1); g_etok[s_eoff[e1] + pos] = t;
}

// ---------------------------------------------------------------------------
// Fused conversion + router. Block b<8192 handles token row b:
// x hi/lo split AND router logits (block reduce) + softmax/top-2.
// Other blocks do 64x32 weight transposes (uint4 stores).
// grid = 8192 + 1024 (w1) + 4096 (w2) + 2048 (w3) = 15360, block 256
// ---------------------------------------------------------------------------
__device__ __forceinline__ void transpose_tile64(const float* __restrict__ W,
                                                 __nv_bfloat16* __restrict__ oh,
                                                 __nv_bfloat16* __restrict__ ol,
                                                 int K, int N, int k0, int n0,
                                                 float (*sm)[33]) {
    int c = threadIdx.x & 31, r0 = threadIdx.x >> 5;
#pragma unroll
    for (int j = 0; j < 8; j++)
        sm[r0 + 8 * j][c] = W[(size_t)(k0 + r0 + 8 * j) * N + n0 + c];
    __syncthreads();
    int n = threadIdx.x >> 3, k8 = (threadIdx.x & 7) * 8;
    __nv_bfloat16 h8[8], l8[8];
#pragma unroll
    for (int i = 0; i < 8; i++) split_bf16(sm[k8 + i][n], h8[i], l8[i]);
    size_t o = (size_t)(n0 + n) * K + k0 + k8;
    *reinterpret_cast<uint4*>(oh + o) = *reinterpret_cast<uint4*>(h8);
    *reinterpret_cast<uint4*>(ol + o) = *reinterpret_cast<uint4*>(l8);
}

__global__ void convert_all_kernel(const float* __restrict__ x,
                                   const float* __restrict__ w1,
                                   const float* __restrict__ w2,
                                   const float* __restrict__ w3,
                                   const float* __restrict__ rw,
                                   const float* __restrict__ rb) {
    __shared__ float sm[64][33];
    __shared__ float rsum[8][8];
    int b = blockIdx.x;
    if (b < 8192) {
        const int tid = threadIdx.x;
        size_t i = (size_t)b * 256 + tid;
        float4 v = reinterpret_cast<const float4*>(x)[i];

        // ---- router partials: thread tid covers h = 4*tid .. 4*tid+3 ----
        float p[NE];
        {
            const float4* w0 = reinterpret_cast<const float4*>(rw + (size_t)(tid * 4) * NE);
            float4 a0 = w0[0], a1 = w0[1];
            float4 b0 = w0[2], b1 = w0[3];
            float4 c0 = w0[4], c1 = w0[5];
            float4 d0 = w0[6], d1 = w0[7];
            p[0] = v.x*a0.x + v.y*b0.x + v.z*c0.x + v.w*d0.x;
            p[1] = v.x*a0.y + v.y*b0.y + v.z*c0.y + v.w*d0.y;
            p[2] = v.x*a0.z + v.y*b0.z + v.z*c0.z + v.w*d0.z;
            p[3] = v.x*a0.w + v.y*b0.w + v.z*c0.w + v.w*d0.w;
            p[4] = v.x*a1.x + v.y*b1.x + v.z*c1.x + v.w*d1.x;
            p[5] = v.x*a1.y + v.y*b1.y + v.z*c1.y + v.w*d1.y;
            p[6] = v.x*a1.z + v.y*b1.z + v.z*c1.z + v.w*d1.z;
            p[7] = v.x*a1.w + v.y*b1.w + v.z*c1.w + v.w*d1.w;
        }
#pragma unroll
        for (int e = 0; e < NE; e++) {
#pragma unroll
            for (int o = 16; o > 0; o >>= 1)
                p[e] += __shfl_xor_sync(0xffffffffu, p[e], o);
        }
        int lane = tid & 31, wrp = tid >> 5;
        if (lane == 0) {
#pragma unroll
            for (int e = 0; e < NE; e++) rsum[wrp][e] = p[e];
        }

        // ---- x hi/lo split (independent of reduce) ----
        {
            __nv_bfloat16 h0, h1, h2, h3, l0, l1, l2, l3;
            split_bf16(v.x, h0, l0); split_bf16(v.y, h1, l1);
            split_bf16(v.z, h2, l2); split_bf16(v.w, h3, l3);
            __nv_bfloat162* ph = reinterpret_cast<__nv_bfloat162*>(g_xh) + 2 * i;
            __nv_bfloat162* pl = reinterpret_cast<__nv_bfloat162*>(g_xl) + 2 * i;
            __nv_bfloat162 a; a.x = h0; a.y = h1; ph[0] = a;
            __nv_bfloat162 bb; bb.x = h2; bb.y = h3; ph[1] = bb;
            __nv_bfloat162 c; c.x = l0; c.y = l1; pl[0] = c;
            __nv_bfloat162 d; d.x = l2; d.y = l3; pl[1] = d;
        }
        __syncthreads();

        if (tid == 0) {
            float lg[NE], m = -1e30f;
#pragma unroll
            for (int e = 0; e < NE; e++) {
                float s = rsum[0][e];
#pragma unroll
                for (int w2i = 1; w2i < 8; w2i++) s += rsum[w2i][e];
                lg[e] = s + rb[e];
                m = fmaxf(m, lg[e]);
            }
            float pr[NE], s = 0.f;
#pragma unroll
            for (int e = 0; e < NE; e++) { pr[e] = expf(lg[e] - m); s += pr[e]; }
            float inv = 1.f / s;
            int i0 = 0;
#pragma unroll
            for (int e = 1; e < NE; e++) if (pr[e] > pr[i0]) i0 = e;
            int i1 = (i0 == 0) ? 1 : 0;
#pragma unroll
            for (int e = 0; e < NE; e++) { if (e == i0) continue; if (pr[e] > pr[i1]) i1 = e; }
#pragma unroll
            for (int e = 0; e < NE; e++)
                g_mw[b * NE + e] = (e == i0 || e == i1) ? pr[e] * inv : 0.f;
            int e0 = min(i0, i1), e1 = max(i0, i1);
            int pid = e0 * (2 * NE - e0 - 1) / 2 + (e1 - e0 - 1);
            g_e0t[b] = e0; g_e1t[b] = e1; g_pidt[b] = pid;
            atomicAdd(&g_pcnt[pid], 1);
            atomicAdd(&g_ecnt[e0], 1);
            atomicAdd(&g_ecnt[e1], 1);
        }
    } else if (b < 8192 + 1024) {
        int t2 = b - 8192;
        int e = t2 >> 7, r = t2 & 127;
        int bx = r & 7, by = r >> 3;
        transpose_tile64(w1 + (size_t)e * HID * RNK,
                         g_w1h + (size_t)e * RNK * HID,
                         g_w1l + (size_t)e * RNK * HID,
                         HID, RNK, by * 64, bx * 32, sm);
    } else if (b < 8192 + 1024 + 4096) {
        int t2 = b - 9216;
        int bx = t2 & 127, by = t2 >> 7;
        transpose_tile64(w2, g_w2h, g_w2l, ERK, FFN, by * 64, bx * 32, sm);
    } else {
        int t2 = b - 13312;
        int bx = t2 & 31, by = t2 >> 5;
        transpose_tile64(w3, g_w3h, g_w3l, FFN, HID, by * 64, bx * 32, sm);
    }
}

// ---------------------------------------------------------------------------
// Gather-GEMM, 128x256 CTA tile, 512 threads (16 warps), warp tile 32x64.
// 2-stage cp.async pipeline, 3-slot rotating B fragments,
// TERM-MAJOR MMA order (same-accumulator reuse distance 1 -> 4).
// MODE 1: t = (x @ w1[e]) * mw   (grid 1 x MAXT1)
// MODE 2: h = gelu(t @ w2slice)  (grid 16 x MAXT2, K=512 pair-gathered)
// MODE 3: out = h @ lin2 + b     (grid 4 x 64, dense)
// ---------------------------------------------------------------------------
template <int MODE>
__global__ void __launch_bounds__(NTHREADS, 1)
mma_gemm(const float* __restrict__ bias, float* __restrict__ Cf) {
    __shared__ int ts[128];
    __shared__ float smw[128];
    extern __shared__ char smem[];
    const uint32_t sbase = s2u(smem);
    const int tid = threadIdx.x;
    const int lane = tid & 31;
    const int wid = tid >> 5;
    const int wm = wid & 3;
    const int wn = wid >> 2;

    int nrows = 128;
    int e = 0, e0 = 0, e1 = 0;
    if (MODE == 1) {
        if ((int)blockIdx.y >= g_meta[0]) return;
        e = g_t1grp[blockIdx.y];
        int r0 = g_t1row[blockIdx.y];
        nrows = min(128, g_ecnt[e] - r0);
        if (tid < 128) {
            int idx = g_eoff[e] + r0 + ((tid < nrows) ? tid : 0);
            int tk = g_etok[idx];
            ts[tid] = tk;
            smw[tid] = g_mw[tk * NE + e];
        }
    } else if (MODE == 2) {
        if ((int)blockIdx.y >= g_meta[1]) return;
        int p = g_t2grp[blockIdx.y];
        int r0 = g_t2row[blockIdx.y];
        nrows = min(128, g_pcnt[p] - r0);
        e0 = g_pe0[p]; e1 = g_pe1[p];
        if (tid < 128)
            ts[tid] = g_ptok[g_poff[p] + r0 + ((tid < nrows) ? tid : 0)];
    } else {
        if (tid < 128) ts[tid] = blockIdx.y * 128 + tid;
    }
    __syncthreads();

    const __nv_bfloat16 *Ahp, *Alp, *Bhp, *Blp;
    int ldA, ldB, brow0, NC;
    if (MODE == 1) {
        Ahp = g_xh; Alp = g_xl; ldA = HID;
        Bhp = g_w1h; Blp = g_w1l; ldB = HID;
        brow0 = e * 256;
        NC = HID / 32;
    } else if (MODE == 2) {
        Ahp = g_th; Alp = g_tl; ldA = ERK;
        Bhp = g_w2h; Blp = g_w2l; ldB = ERK;
        brow0 = blockIdx.x * 256;
        NC = 512 / 32;
    } else {
        Ahp = g_hh; Alp = g_hl; ldA = FFN;
        Bhp = g_w3h; Blp = g_w3l; ldB = FFN;
        brow0 = blockIdx.x * 256;
        NC = FFN / 32;
    }

    const int r0s = tid >> 2, q0 = tid & 3;
    const size_t aoff0 = (size_t)ts[r0s] * ldA + q0 * 8;
    const size_t boff0 = (size_t)(brow0 + r0s) * ldB + q0 * 8;
    const size_t boff1 = (size_t)(brow0 + r0s + 128) * ldB + q0 * 8;

    const __nv_bfloat16 *pAh = Ahp + aoff0, *pAl = Alp + aoff0;
    const __nv_bfloat16 *pB0h = Bhp + boff0, *pB0l = Blp + boff0;
    const __nv_bfloat16 *pB1h = Bhp + boff1, *pB1l = Blp + boff1;
    const uint32_t dA  = (uint32_t)(r0s * ROWB + q0 * 16);
    const uint32_t dB0 = (uint32_t)(2 * A_T + r0s * ROWB + q0 * 16);
    const uint32_t dB1 = dB0 + (uint32_t)(128 * ROWB);

    float acc[2][8][4];
#pragma unroll
    for (int i = 0; i < 2; i++)
#pragma unroll
        for (int j = 0; j < 8; j++)
#pragma unroll
            for (int k = 0; k < 4; k++) acc[i][j][k] = 0.f;

    auto kseg = [&](int c) -> size_t {
        if (MODE == 2)
            return (c < 8) ? (size_t)e0 * 256 + (size_t)c * 32
                           : (size_t)e1 * 256 + (size_t)(c - 8) * 32;
        return (size_t)c * 32;
    };

    auto load_chunk = [&](int c, int st) {
        const size_t ko = kseg(c);
        const uint32_t s = sbase + (uint32_t)st * STG;
        cp16(s + dA,        pAh + ko);
        cp16(s + dA + A_T,  pAl + ko);
        cp16(s + dB0,       pB0h + ko);
        cp16(s + dB0 + B_T, pB0l + ko);
        cp16(s + dB1,       pB1h + ko);
        cp16(s + dB1 + B_T, pB1l + ko);
        cp_commit();
    };

    load_chunk(0, 0);

    const int g = lane >> 3, lr = lane & 7;
    int aofs[2], bofs[4];
#pragma unroll
    for (int mt = 0; mt < 2; mt++)
        aofs[mt] = (wm * 32 + mt * 16 + (g & 1) * 8 + lr) * ROWB + (g >> 1) * 16;
#pragma unroll
    for (int np = 0; np < 4; np++)
        bofs[np] = (wn * 64 + np * 16 + (g >> 1) * 8 + lr) * ROWB + (g & 1) * 16;

    for (int c = 0; c < NC; c++) {
        cp_wait<0>();
        __syncthreads();
        const uint32_t sA = sbase + (uint32_t)((c & 1) * STG);
        const uint32_t sB = sA + (uint32_t)(2 * A_T);
        const bool have_next = (c + 1 < NC);

        uint32_t afh[2][4], afl[2][4];
        uint32_t bfh[3][4], bfl[3][4];
#pragma unroll
        for (int mt = 0; mt < 2; mt++) {
            ldsm4(afh[mt], sA + aofs[mt]);
            ldsm4(afl[mt], sA + aofs[mt] + A_T);
        }
        ldsm4(bfh[0], sB + bofs[0]);
        ldsm4(bfl[0], sB + bofs[0] + B_T);

#pragma unroll
        for (int ks = 0; ks < 2; ks++) {
#pragma unroll
            for (int np = 0; np < 4; np++) {
                const int j = ks * 4 + np;
                const int cs = j % 3, ns = (j + 1) % 3;
                if (np < 3) {
                    ldsm4(bfh[ns], sB + bofs[np + 1] + ks * 32);
                    ldsm4(bfl[ns], sB + bofs[np + 1] + ks * 32 + B_T);
                } else if (ks == 0) {
                    ldsm4(bfh[ns], sB + bofs[0] + 32);
                    ldsm4(bfl[ns], sB + bofs[0] + 32 + B_T);
                }
                // TERM-MAJOR: 4 independent MMAs between same-acc reuses
#pragma unroll
                for (int term = 0; term < 3; term++) {
#pragma unroll
                    for (int mt = 0; mt < 2; mt++) {
#pragma unroll
                        for (int h2 = 0; h2 < 2; h2++) {
                            float* cc = acc[mt][np * 2 + h2];
                            const uint32_t* aa = (term == 2) ? afl[mt] : afh[mt];
                            const uint32_t* bb = (term == 1) ? (bfl[cs] + h2 * 2)
                                                             : (bfh[cs] + h2 * 2);
                            mma16816(cc, aa, bb);
                        }
                    }
                }
                if (ks == 0 && np == 0 && have_next) load_chunk(c + 1, (c + 1) & 1);
            }
            if (ks == 0) {
#pragma unroll
                for (int mt = 0; mt < 2; mt++) {
                    ldsm4(afh[mt], sA + aofs[mt] + 32);
                    ldsm4(afl[mt], sA + aofs[mt] + 32 + A_T);
                }
            }
        }
    }

    // Epilogue
#pragma unroll
    for (int mt = 0; mt < 2; mt++) {
#pragma unroll
        for (int half = 0; half < 2; half++) {
            const int rl = wm * 32 + mt * 16 + half * 8 + (lane >> 2);
            const bool valid = rl < nrows;
            const int tok = ts[rl];
            float s = 1.f;
            if (MODE == 1) s = smw[rl];
            size_t rbase;
            if (MODE == 1)      rbase = (size_t)tok * ERK + e * 256;
            else if (MODE == 2) rbase = (size_t)tok * FFN + blockIdx.x * 256;
            else                rbase = (size_t)tok * HID + blockIdx.x * 256;
#pragma unroll
            for (int nt = 0; nt < 8; nt++) {
                const int col = wn * 64 + nt * 8 + (lane & 3) * 2;
                float v0 = acc[mt][nt][half * 2 + 0];
                float v1 = acc[mt][nt][half * 2 + 1];
                if (MODE == 3) {
                    if (valid) {
                        float2 o;
                        o.x = v0 + bias[blockIdx.x * 256 + col];
                        o.y = v1 + bias[blockIdx.x * 256 + col + 1];
                        *reinterpret_cast<float2*>(Cf + rbase + col) = o;
                    }
                } else {
                    if (MODE == 1) { v0 *= s; v1 *= s; }
                    else {
                        v0 = 0.5f * v0 * (1.f + erff(v0 * 0.70710678118654752f));
                        v1 = 0.5f * v1 * (1.f + erff(v1 * 0.70710678118654752f));
                    }
                    if (valid) {
                        __nv_bfloat16 h0, h1, l0, l1;
                        split_bf16(v0, h0, l0); split_bf16(v1, h1, l1);
                        __nv_bfloat162 hp; hp.x = h0; hp.y = h1;
                        __nv_bfloat162 lp; lp.x = l0; lp.y = l1;
                        __nv_bfloat16* Ch = (MODE == 1) ? g_th : g_hh;
                        __nv_bfloat16* Cl = (MODE == 1) ? g_tl : g_hl;
                        *reinterpret_cast<__nv_bfloat162*>(Ch + rbase + col) = hp;
                        *reinterpret_cast<__nv_bfloat162*>(Cl + rbase + col) = lp;
                    }
                }
            }
        }
    }
}

// ---------------------------------------------------------------------------
extern "C" void kernel_launch(void* const* d_in, const int* in_sizes, int n_in,
                              void* d_out, int out_size) {
    const float* x        = (const float*)d_in[0];
    const float* router_w = (const float*)d_in[1];
    const float* router_b = (const float*)d_in[2];
    const float* w1       = (const float*)d_in[3];
    const float* w2       = (const float*)d_in[4];
    const float* lin2_w   = (const float*)d_in[5];
    const float* lin2_b   = (const float*)d_in[6];
    float* out = (float*)d_out;

    cudaFuncSetAttribute(mma_gemm<1>, cudaFuncAttributeMaxDynamicSharedMemorySize, SMEM_BYTES);
    cudaFuncSetAttribute(mma_gemm<2>, cudaFuncAttributeMaxDynamicSharedMemorySize, SMEM_BYTES);
    cudaFuncSetAttribute(mma_gemm<3>, cudaFuncAttributeMaxDynamicSharedMemorySize, SMEM_BYTES);

    zero_kernel<<<1, 32>>>();                                               // 0
    convert_all_kernel<<<15360, 256>>>(x, w1, w2, lin2_w,
                                       router_w, router_b);                 // 1 (router fused)
    scatter_kernel<<<TOK / 256, 256>>>();                                   // 2

    // Stage 1 (sparse, per-expert, N=256): t = (x @ w1[e]) * mw
    mma_gemm<1><<<dim3(1, MAXT1), NTHREADS, SMEM_BYTES>>>(nullptr, nullptr);          // 3
    // Stage 2 (sparse, per-pair, K=512): h = gelu(t @ w2)
    mma_gemm<2><<<dim3(FFN / 256, MAXT2), NTHREADS, SMEM_BYTES>>>(nullptr, nullptr);  // 4
    // Stage 3 (dense): out = h @ lin2 + b
    mma_gemm<3><<<dim3(HID / 256, TOK / 128), NTHREADS, SMEM_BYTES>>>(lin2_b, out);   // 5
}

// round 17
// speedup vs baseline: 1.1699x; 1.1409x over previous
#include <cuda_runtime.h>
#include <cuda_bf16.h>
#include <stdint.h>
#include <math.h>

#define TOK 8192
#define HID 1024
#define RNK 256
#define FFN 4096
#define NE  8
#define ERK (NE*RNK)  // 2048
#define NPAIR 28
#define MAXT1 136
#define MAXT2 92

#define NTHREADS 512
#define ROWB 144                   // 32 tf32 = 128B + 16B pad (bank stride 4r)
#define A_T (128*ROWB)             // 18432
#define B_T (256*ROWB)             // 36864
#define STG (A_T + B_T)            // 55296
#define SMEM_BYTES (2*STG)         // 110592

// ---------------------------------------------------------------------------
// Scratch (device globals)
// ---------------------------------------------------------------------------
__device__ float g_mw[TOK * NE];
__device__ int g_e0t[TOK], g_e1t[TOK], g_pidt[TOK];
__device__ int g_pcnt[NPAIR], g_poff[NPAIR], g_pfill[NPAIR], g_ptok[TOK];
__device__ int g_ecnt[NE], g_eoff[NE], g_efill[NE], g_etok[2 * TOK];
__device__ int g_t1grp[MAXT1], g_t1row[MAXT1];
__device__ int g_t2grp[MAXT2], g_t2row[MAXT2];
__device__ int g_pe0[NPAIR], g_pe1[NPAIR];
__device__ int g_meta[2];

// tf32-rounded fp32 operands
__device__ float g_xt[(size_t)TOK * HID];
__device__ float g_tt[(size_t)TOK * ERK];
__device__ float g_ht[(size_t)TOK * FFN];
__device__ float g_w1t[(size_t)ERK * HID];   // [2048,1024] (N,K)
__device__ float g_w2t[(size_t)FFN * ERK];   // [4096,2048]
__device__ float g_w3t[(size_t)HID * FFN];   // [1024,4096]

// ---------------------------------------------------------------------------
// PTX helpers (base sm_103 target)
// ---------------------------------------------------------------------------
__device__ __forceinline__ uint32_t s2u(const void* p) {
    uint32_t a;
    asm("{ .reg .u64 t; cvta.to.shared.u64 t, %1; cvt.u32.u64 %0, t; }" : "=r"(a) : "l"(p));
    return a;
}
__device__ __forceinline__ void cp16(uint32_t dst, const void* src) {
    asm volatile("cp.async.cg.shared.global [%0], [%1], 16;" :: "r"(dst), "l"(src) : "memory");
}
__device__ __forceinline__ void cp_commit() {
    asm volatile("cp.async.commit_group;" ::: "memory");
}
template <int N>
__device__ __forceinline__ void cp_wait() {
    asm volatile("cp.async.wait_group %0;" :: "n"(N) : "memory");
}
__device__ __forceinline__ void ldsm4(uint32_t* r, uint32_t addr) {
    asm volatile("ldmatrix.sync.aligned.m8n8.x4.shared.b16 {%0,%1,%2,%3}, [%4];"
                 : "=r"(r[0]), "=r"(r[1]), "=r"(r[2]), "=r"(r[3]) : "r"(addr));
}
__device__ __forceinline__ void mma_tf32(float* c, const uint32_t* a, const uint32_t* b) {
    asm volatile(
        "mma.sync.aligned.m16n8k8.row.col.f32.tf32.tf32.f32 "
        "{%0,%1,%2,%3}, {%4,%5,%6,%7}, {%8,%9}, {%0,%1,%2,%3};"
        : "+f"(c[0]), "+f"(c[1]), "+f"(c[2]), "+f"(c[3])
        : "r"(a[0]), "r"(a[1]), "r"(a[2]), "r"(a[3]), "r"(b[0]), "r"(b[1]));
}
__device__ __forceinline__ float cvt_tf32(float v) {
    uint32_t o;
    asm("cvt.rna.tf32.f32 %0, %1;" : "=r"(o) : "f"(v));
    return __uint_as_float(o);
}

// ---------------------------------------------------------------------------
// Routing infrastructure
// ---------------------------------------------------------------------------
__global__ void zero_kernel() {
    int i = threadIdx.x;
    if (i < NPAIR) { g_pcnt[i] = 0; g_pfill[i] = 0; }
    if (i < NE)    { g_ecnt[i] = 0; g_efill[i] = 0; }
}

__global__ void scatter_kernel() {
    __shared__ int s_eoff[NE], s_poff[NPAIR];
    if (threadIdx.x == 0) {
        int off = 0;
#pragma unroll
        for (int e2 = 0; e2 < NE; e2++) { s_eoff[e2] = off; off += g_ecnt[e2]; }
        off = 0;
#pragma unroll
        for (int p = 0; p < NPAIR; p++) { s_poff[p] = off; off += g_pcnt[p]; }
    }
    __syncthreads();

    if (blockIdx.x == 0 && threadIdx.x == 0) {
        int nt = 0;
        for (int e2 = 0; e2 < NE; e2++) {
            g_eoff[e2] = s_eoff[e2];
            for (int r = 0; r < g_ecnt[e2]; r += 128) { g_t1grp[nt] = e2; g_t1row[nt] = r; nt++; }
        }
        g_meta[0] = nt;
        nt = 0;
        int p = 0;
        for (int a = 0; a < NE; a++)
            for (int b = a + 1; b < NE; b++) {
                g_pe0[p] = a; g_pe1[p] = b; g_poff[p] = s_poff[p];
                for (int r = 0; r < g_pcnt[p]; r += 128) { g_t2grp[nt] = p; g_t2row[nt] = r; nt++; }
                p++;
            }
        g_meta[1] = nt;
    }

    int t = blockIdx.x * blockDim.x + threadIdx.x;
    if (t >= TOK) return;
    int pid = g_pidt[t];
    int pos = atomicAdd(&g_pfill[pid], 1);
    g_ptok[s_poff[pid] + pos] = t;
    int e0 = g_e0t[t], e1 = g_e1t[t];
    pos = atomicAdd(&g_efill[e0], 1); g_etok[s_eoff[e0] + pos] = t;
    pos = atomicAdd(&g_efill[e1], 1); g_etok[s_eoff[e1] + pos] = t;
}

// ---------------------------------------------------------------------------
// Fused conversion + router.
// Blocks <8192: token row b — tf32-round x + router logits/top2.
// Others: weight transpose 64x32 tiles -> [N,K] fp32(tf32-rounded).
// grid = 8192 + 1024 (w1) + 4096 (w2) + 2048 (w3) = 15360, block 256
// ---------------------------------------------------------------------------
__device__ __forceinline__ void transpose_tile64(const float* __restrict__ W,
                                                 float* __restrict__ ot,
                                                 int K, int N, int k0, int n0,
                                                 float (*sm)[33]) {
    int c = threadIdx.x & 31, r0 = threadIdx.x >> 5;
#pragma unroll
    for (int j = 0; j < 8; j++)
        sm[r0 + 8 * j][c] = W[(size_t)(k0 + r0 + 8 * j) * N + n0 + c];
    __syncthreads();
    int n = threadIdx.x >> 3, k8 = (threadIdx.x & 7) * 8;
    float o8[8];
#pragma unroll
    for (int i = 0; i < 8; i++) o8[i] = cvt_tf32(sm[k8 + i][n]);
    size_t o = (size_t)(n0 + n) * K + k0 + k8;
    *reinterpret_cast<float4*>(ot + o)     = *reinterpret_cast<float4*>(o8);
    *reinterpret_cast<float4*>(ot + o + 4) = *reinterpret_cast<float4*>(o8 + 4);
}

__global__ void convert_all_kernel(const float* __restrict__ x,
                                   const float* __restrict__ w1,
                                   const float* __restrict__ w2,
                                   const float* __restrict__ w3,
                                   const float* __restrict__ rw,
                                   const float* __restrict__ rb) {
    __shared__ float sm[64][33];
    __shared__ float rsum[8][8];
    int b = blockIdx.x;
    if (b < 8192) {
        const int tid = threadIdx.x;
        size_t i = (size_t)b * 256 + tid;
        float4 v = reinterpret_cast<const float4*>(x)[i];

        // router partials: thread tid covers h = 4*tid..4*tid+3
        float p[NE];
        {
            const float4* w0 = reinterpret_cast<const float4*>(rw + (size_t)(tid * 4) * NE);
            float4 a0 = w0[0], a1 = w0[1];
            float4 b0 = w0[2], b1 = w0[3];
            float4 c0 = w0[4], c1 = w0[5];
            float4 d0 = w0[6], d1 = w0[7];
            p[0] = v.x*a0.x + v.y*b0.x + v.z*c0.x + v.w*d0.x;
            p[1] = v.x*a0.y + v.y*b0.y + v.z*c0.y + v.w*d0.y;
            p[2] = v.x*a0.z + v.y*b0.z + v.z*c0.z + v.w*d0.z;
            p[3] = v.x*a0.w + v.y*b0.w + v.z*c0.w + v.w*d0.w;
            p[4] = v.x*a1.x + v.y*b1.x + v.z*c1.x + v.w*d1.x;
            p[5] = v.x*a1.y + v.y*b1.y + v.z*c1.y + v.w*d1.y;
            p[6] = v.x*a1.z + v.y*b1.z + v.z*c1.z + v.w*d1.z;
            p[7] = v.x*a1.w + v.y*b1.w + v.z*c1.w + v.w*d1.w;
        }
#pragma unroll
        for (int e = 0; e < NE; e++) {
#pragma unroll
            for (int o = 16; o > 0; o >>= 1)
                p[e] += __shfl_xor_sync(0xffffffffu, p[e], o);
        }
        int lane = tid & 31, wrp = tid >> 5;
        if (lane == 0) {
#pragma unroll
            for (int e = 0; e < NE; e++) rsum[wrp][e] = p[e];
        }

        // x tf32 rounding
        {
            float4 o;
            o.x = cvt_tf32(v.x); o.y = cvt_tf32(v.y);
            o.z = cvt_tf32(v.z); o.w = cvt_tf32(v.w);
            reinterpret_cast<float4*>(g_xt)[i] = o;
        }
        __syncthreads();

        if (tid == 0) {
            float lg[NE], m = -1e30f;
#pragma unroll
            for (int e = 0; e < NE; e++) {
                float s = rsum[0][e];
#pragma unroll
                for (int w2i = 1; w2i < 8; w2i++) s += rsum[w2i][e];
                lg[e] = s + rb[e];
                m = fmaxf(m, lg[e]);
            }
            float pr[NE], s = 0.f;
#pragma unroll
            for (int e = 0; e < NE; e++) { pr[e] = expf(lg[e] - m); s += pr[e]; }
            float inv = 1.f / s;
            int i0 = 0;
#pragma unroll
            for (int e = 1; e < NE; e++) if (pr[e] > pr[i0]) i0 = e;
            int i1 = (i0 == 0) ? 1 : 0;
#pragma unroll
            for (int e = 0; e < NE; e++) { if (e == i0) continue; if (pr[e] > pr[i1]) i1 = e; }
#pragma unroll
            for (int e = 0; e < NE; e++)
                g_mw[b * NE + e] = (e == i0 || e == i1) ? pr[e] * inv : 0.f;
            int e0 = min(i0, i1), e1 = max(i0, i1);
            int pid = e0 * (2 * NE - e0 - 1) / 2 + (e1 - e0 - 1);
            g_e0t[b] = e0; g_e1t[b] = e1; g_pidt[b] = pid;
            atomicAdd(&g_pcnt[pid], 1);
            atomicAdd(&g_ecnt[e0], 1);
            atomicAdd(&g_ecnt[e1], 1);
        }
    } else if (b < 8192 + 1024) {
        int t2 = b - 8192;
        int e = t2 >> 7, r = t2 & 127;
        int bx = r & 7, by = r >> 3;
        transpose_tile64(w1 + (size_t)e * HID * RNK,
                         g_w1t + (size_t)e * RNK * HID,
                         HID, RNK, by * 64, bx * 32, sm);
    } else if (b < 8192 + 1024 + 4096) {
        int t2 = b - 9216;
        int bx = t2 & 127, by = t2 >> 7;
        transpose_tile64(w2, g_w2t, ERK, FFN, by * 64, bx * 32, sm);
    } else {
        int t2 = b - 13312;
        int bx = t2 & 31, by = t2 >> 5;
        transpose_tile64(w3, g_w3t, FFN, HID, by * 64, bx * 32, sm);
    }
}

// ---------------------------------------------------------------------------
// TF32 gather-GEMM, 128x256 CTA tile, 512 threads, warp tile 32x64.
// Single-pass tf32 m16n8k8 (2 MMAs per K16 vs 3 with bf16-split).
// MODE 1: t = (x @ w1[e]) * mw   (grid 1 x MAXT1)
// MODE 2: h = gelu(t @ w2slice)  (grid 16 x MAXT2, K=512 pair-gathered)
// MODE 3: out = h @ lin2 + b     (grid 4 x 64, dense)
// ---------------------------------------------------------------------------
template <int MODE>
__global__ void __launch_bounds__(NTHREADS, 1)
mma_gemm(const float* __restrict__ bias, float* __restrict__ Cf) {
    __shared__ int ts[128];
    __shared__ float smw[128];
    extern __shared__ char smem[];
    const uint32_t sbase = s2u(smem);
    const int tid = threadIdx.x;
    const int lane = tid & 31;
    const int wid = tid >> 5;
    const int wm = wid & 3;           // 4 warps over M (32 rows)
    const int wn = wid >> 2;          // 4 warps over N (64 cols)

    int nrows = 128;
    int e = 0, e0 = 0, e1 = 0;
    if (MODE == 1) {
        if ((int)blockIdx.y >= g_meta[0]) return;
        e = g_t1grp[blockIdx.y];
        int r0 = g_t1row[blockIdx.y];
        nrows = min(128, g_ecnt[e] - r0);
        if (tid < 128) {
            int idx = g_eoff[e] + r0 + ((tid < nrows) ? tid : 0);
            int tk = g_etok[idx];
            ts[tid] = tk;
            smw[tid] = g_mw[tk * NE + e];
        }
    } else if (MODE == 2) {
        if ((int)blockIdx.y >= g_meta[1]) return;
        int p = g_t2grp[blockIdx.y];
        int r0 = g_t2row[blockIdx.y];
        nrows = min(128, g_pcnt[p] - r0);
        e0 = g_pe0[p]; e1 = g_pe1[p];
        if (tid < 128)
            ts[tid] = g_ptok[g_poff[p] + r0 + ((tid < nrows) ? tid : 0)];
    } else {
        if (tid < 128) ts[tid] = blockIdx.y * 128 + tid;
    }
    __syncthreads();

    const float *Ap, *Bp;
    int ldA, ldB, brow0, NC;
    if (MODE == 1) {
        Ap = g_xt; ldA = HID; Bp = g_w1t; ldB = HID;
        brow0 = e * 256; NC = HID / 32;
    } else if (MODE == 2) {
        Ap = g_tt; ldA = ERK; Bp = g_w2t; ldB = ERK;
        brow0 = blockIdx.x * 256; NC = 512 / 32;
    } else {
        Ap = g_ht; ldA = FFN; Bp = g_w3t; ldB = FFN;
        brow0 = blockIdx.x * 256; NC = FFN / 32;
    }

    const int r0s = tid >> 2, q0 = tid & 3;          // r0s 0..127
    const float* pA  = Ap + (size_t)ts[r0s] * ldA + q0 * 4;
    const float* pB0 = Bp + (size_t)(brow0 + r0s) * ldB + q0 * 4;
    const float* pB1 = Bp + (size_t)(brow0 + r0s + 128) * ldB + q0 * 4;
    const uint32_t dA  = (uint32_t)(r0s * ROWB + q0 * 16);
    const uint32_t dB0 = (uint32_t)(A_T + r0s * ROWB + q0 * 16);
    const uint32_t dB1 = dB0 + (uint32_t)(128 * ROWB);

    float acc[2][8][4];
#pragma unroll
    for (int i = 0; i < 2; i++)
#pragma unroll
        for (int j = 0; j < 8; j++)
#pragma unroll
            for (int k = 0; k < 4; k++) acc[i][j][k] = 0.f;

    auto kseg = [&](int c) -> size_t {
        if (MODE == 2)
            return (c < 8) ? (size_t)e0 * 256 + (size_t)c * 32
                           : (size_t)e1 * 256 + (size_t)(c - 8) * 32;
        return (size_t)c * 32;
    };

    auto load_chunk = [&](int c, int st) {
        const size_t ko = kseg(c);
        const uint32_t s = sbase + (uint32_t)st * STG;
        cp16(s + dA,       pA + ko);
        cp16(s + dA + 64,  pA + ko + 16);
        cp16(s + dB0,      pB0 + ko);
        cp16(s + dB0 + 64, pB0 + ko + 16);
        cp16(s + dB1,      pB1 + ko);
        cp16(s + dB1 + 64, pB1 + ko + 16);
        cp_commit();
    };

    load_chunk(0, 0);

    // ldsm base offsets (per warp, per lane)
    // A tile (m16 x k8): matrices sel: row += (sel&1)*8, kofs += (sel>>1)*16
    int aofs[2];
#pragma unroll
    for (int mt = 0; mt < 2; mt++)
        aofs[mt] = (wm * 32 + mt * 16 + (lane & 7) + ((lane >> 3) & 1) * 8) * ROWB
                 + ((lane >> 4) & 1) * 16;
    // B pair (n16 block -> n-tiles n0, n0+8): row += (sel>>1)*8, kofs += (sel&1)*16
    int bofs[4];
#pragma unroll
    for (int p = 0; p < 4; p++)
        bofs[p] = (wn * 64 + p * 16 + (lane & 7) + ((lane >> 4) & 1) * 8) * ROWB
                + ((lane >> 3) & 1) * 16;

    for (int c = 0; c < NC; c++) {
        cp_wait<0>();
        __syncthreads();
        const uint32_t sA = sbase + (uint32_t)((c & 1) * STG);
        const uint32_t sB = sA + (uint32_t)A_T;
        const bool have_next = (c + 1 < NC);

        uint32_t af[2][2][4];          // [step&1][mt][4]
        uint32_t bf[3][4];             // rotating: r0,r1 = n0; r2,r3 = n0+8
#pragma unroll
        for (int mt = 0; mt < 2; mt++) ldsm4(af[0][mt], sA + aofs[mt]);
        ldsm4(bf[0], sB + bofs[0]);

#pragma unroll
        for (int s = 0; s < 4; s++) {
            const int sb = s & 1;
#pragma unroll
            for (int p = 0; p < 4; p++) {
                const int j = s * 4 + p;
                const int cs = j % 3, ns = (j + 1) % 3;
                if (p < 3) {
                    ldsm4(bf[ns], sB + bofs[p + 1] + s * 32);
                } else if (s < 3) {
                    ldsm4(bf[ns], sB + bofs[0] + (s + 1) * 32);
                }
                // A(s+1) prefetch spread over p==1,2
                if (s < 3 && p == 1) ldsm4(af[sb ^ 1][0], sA + aofs[0] + (s + 1) * 32);
                if (s < 3 && p == 2) ldsm4(af[sb ^ 1][1], sA + aofs[1] + (s + 1) * 32);
#pragma unroll
                for (int mt = 0; mt < 2; mt++) {
#pragma unroll
                    for (int k2 = 0; k2 < 2; k2++)
                        mma_tf32(acc[mt][2 * p + k2], af[sb][mt], bf[cs] + k2 * 2);
                }
                if (s == 0 && p == 0 && have_next) load_chunk(c + 1, (c + 1) & 1);
            }
        }
    }

    // Epilogue (fragment layout identical to m16n8k16)
#pragma unroll
    for (int mt = 0; mt < 2; mt++) {
#pragma unroll
        for (int half = 0; half < 2; half++) {
            const int rl = wm * 32 + mt * 16 + half * 8 + (lane >> 2);
            const bool valid = rl < nrows;
            const int tok = ts[rl];
            float s = 1.f;
            if (MODE == 1) s = smw[rl];
            size_t rbase;
            if (MODE == 1)      rbase = (size_t)tok * ERK + e * 256;
            else if (MODE == 2) rbase = (size_t)tok * FFN + blockIdx.x * 256;
            else                rbase = (size_t)tok * HID + blockIdx.x * 256;
#pragma unroll
            for (int nt = 0; nt < 8; nt++) {
                const int col = wn * 64 + nt * 8 + (lane & 3) * 2;
                float v0 = acc[mt][nt][half * 2 + 0];
                float v1 = acc[mt][nt][half * 2 + 1];
                if (!valid) continue;
                float2 o;
                if (MODE == 3) {
                    o.x = v0 + bias[blockIdx.x * 256 + col];
                    o.y = v1 + bias[blockIdx.x * 256 + col + 1];
                    *reinterpret_cast<float2*>(Cf + rbase + col) = o;
                } else {
                    if (MODE == 1) { v0 *= s; v1 *= s; }
                    else {
                        v0 = 0.5f * v0 * (1.f + erff(v0 * 0.70710678118654752f));
                        v1 = 0.5f * v1 * (1.f + erff(v1 * 0.70710678118654752f));
                    }
                    o.x = cvt_tf32(v0);
                    o.y = cvt_tf32(v1);
                    float* Ct = (MODE == 1) ? g_tt : g_ht;
                    *reinterpret_cast<float2*>(Ct + rbase + col) = o;
                }
            }
        }
    }
}

// ---------------------------------------------------------------------------
extern "C" void kernel_launch(void* const* d_in, const int* in_sizes, int n_in,
                              void* d_out, int out_size) {
    const float* x        = (const float*)d_in[0];
    const float* router_w = (const float*)d_in[1];
    const float* router_b = (const float*)d_in[2];
    const float* w1       = (const float*)d_in[3];
    const float* w2       = (const float*)d_in[4];
    const float* lin2_w   = (const float*)d_in[5];
    const float* lin2_b   = (const float*)d_in[6];
    float* out = (float*)d_out;

    cudaFuncSetAttribute(mma_gemm<1>, cudaFuncAttributeMaxDynamicSharedMemorySize, SMEM_BYTES);
    cudaFuncSetAttribute(mma_gemm<2>, cudaFuncAttributeMaxDynamicSharedMemorySize, SMEM_BYTES);
    cudaFuncSetAttribute(mma_gemm<3>, cudaFuncAttributeMaxDynamicSharedMemorySize, SMEM_BYTES);

    zero_kernel<<<1, 32>>>();                                               // 0
    convert_all_kernel<<<15360, 256>>>(x, w1, w2, lin2_w,
                                       router_w, router_b);                 // 1
    scatter_kernel<<<TOK / 256, 256>>>();                                   // 2

    // Stage 1 (sparse, per-expert, N=256): t = (x @ w1[e]) * mw
    mma_gemm<1><<<dim3(1, MAXT1), NTHREADS, SMEM_BYTES>>>(nullptr, nullptr);          // 3
    // Stage 2 (sparse, per-pair, K=512): h = gelu(t @ w2)
    mma_gemm<2><<<dim3(FFN / 256, MAXT2), NTHREADS, SMEM_BYTES>>>(nullptr, nullptr);  // 4
    // Stage 3 (dense): out = h @ lin2 + b
    mma_gemm<3><<<dim3(HID / 256, TOK / 128), NTHREADS, SMEM_BYTES>>>(lin2_b, out);   // 5
}